// round 9
// baseline (speedup 1.0000x reference)
#include <cuda_runtime.h>
#include <cstdint>

// MeanAggregatorHead: out[b,:] = (1/K) * sum_k tab[idx[b,k],:]
// B=100000, K=32, N=500000, D=128, fp32 table, int32 indices.
//
// R9: partition fused into pass 0. Pass 0: load raw idx, 4-ballot bucket
// sort by table quarter (64MB chunks -> L2-resident per pass), stage
// reordered idx via per-warp smem, persist to scratch for passes 1-3,
// gather bucket 0 densely. Passes 1-3: dense gathers + red.add partials.
// Gather passes measured at ~12.8TB/s L2 (the LTS cap) in R8.

constexpr int K       = 32;
constexpr int D       = 128;
constexpr int PASSES  = 4;
constexpr int MAX_B   = 100000;
constexpr int WPB     = 8;          // warps per block (256 threads)

__device__ int g_sidx[MAX_B * K];   // bucket-reordered indices (12.8MB)
__device__ int g_cnt [MAX_B];       // packed counts c0|c1<<8|c2<<16 (0.4MB)

__device__ __forceinline__ void red_add_f4(float4* p, float4 v) {
    asm volatile("red.global.add.v4.f32 [%0], {%1,%2,%3,%4};"
                 :: "l"(p), "f"(v.x), "f"(v.y), "f"(v.z), "f"(v.w) : "memory");
}

// Dense gather over slots [start, end) of warp-held reordered index v.
__device__ __forceinline__ float4 dense_gather(
    const float* __restrict__ tab, int v, int lane, int start, int end)
{
    float4 acc = make_float4(0.f, 0.f, 0.f, 0.f);
    int j = start;
    #pragma unroll 1
    for (; j + 8 <= end; j += 8) {             // 8 LDG.128 front-batched
        int r0 = __shfl_sync(0xffffffffu, v, j);
        int r1 = __shfl_sync(0xffffffffu, v, j + 1);
        int r2 = __shfl_sync(0xffffffffu, v, j + 2);
        int r3 = __shfl_sync(0xffffffffu, v, j + 3);
        int r4 = __shfl_sync(0xffffffffu, v, j + 4);
        int r5 = __shfl_sync(0xffffffffu, v, j + 5);
        int r6 = __shfl_sync(0xffffffffu, v, j + 6);
        int r7 = __shfl_sync(0xffffffffu, v, j + 7);
        float4 a0 = __ldg(&reinterpret_cast<const float4*>(tab + (size_t)r0 * D)[lane]);
        float4 a1 = __ldg(&reinterpret_cast<const float4*>(tab + (size_t)r1 * D)[lane]);
        float4 a2 = __ldg(&reinterpret_cast<const float4*>(tab + (size_t)r2 * D)[lane]);
        float4 a3 = __ldg(&reinterpret_cast<const float4*>(tab + (size_t)r3 * D)[lane]);
        float4 a4 = __ldg(&reinterpret_cast<const float4*>(tab + (size_t)r4 * D)[lane]);
        float4 a5 = __ldg(&reinterpret_cast<const float4*>(tab + (size_t)r5 * D)[lane]);
        float4 a6 = __ldg(&reinterpret_cast<const float4*>(tab + (size_t)r6 * D)[lane]);
        float4 a7 = __ldg(&reinterpret_cast<const float4*>(tab + (size_t)r7 * D)[lane]);
        acc.x += ((a0.x + a1.x) + (a2.x + a3.x)) + ((a4.x + a5.x) + (a6.x + a7.x));
        acc.y += ((a0.y + a1.y) + (a2.y + a3.y)) + ((a4.y + a5.y) + (a6.y + a7.y));
        acc.z += ((a0.z + a1.z) + (a2.z + a3.z)) + ((a4.z + a5.z) + (a6.z + a7.z));
        acc.w += ((a0.w + a1.w) + (a2.w + a3.w)) + ((a4.w + a5.w) + (a6.w + a7.w));
    }
    #pragma unroll 1
    for (; j + 4 <= end; j += 4) {
        int r0 = __shfl_sync(0xffffffffu, v, j);
        int r1 = __shfl_sync(0xffffffffu, v, j + 1);
        int r2 = __shfl_sync(0xffffffffu, v, j + 2);
        int r3 = __shfl_sync(0xffffffffu, v, j + 3);
        float4 a0 = __ldg(&reinterpret_cast<const float4*>(tab + (size_t)r0 * D)[lane]);
        float4 a1 = __ldg(&reinterpret_cast<const float4*>(tab + (size_t)r1 * D)[lane]);
        float4 a2 = __ldg(&reinterpret_cast<const float4*>(tab + (size_t)r2 * D)[lane]);
        float4 a3 = __ldg(&reinterpret_cast<const float4*>(tab + (size_t)r3 * D)[lane]);
        acc.x += (a0.x + a1.x) + (a2.x + a3.x);
        acc.y += (a0.y + a1.y) + (a2.y + a3.y);
        acc.z += (a0.z + a1.z) + (a2.z + a3.z);
        acc.w += (a0.w + a1.w) + (a2.w + a3.w);
    }
    #pragma unroll 1
    for (; j < end; ++j) {
        int r = __shfl_sync(0xffffffffu, v, j);
        float4 a = __ldg(&reinterpret_cast<const float4*>(tab + (size_t)r * D)[lane]);
        acc.x += a.x; acc.y += a.y; acc.z += a.z; acc.w += a.w;
    }
    return acc;
}

// Pass 0: partition + gather bucket 0, fused.
__global__ __launch_bounds__(WPB * 32) void partition_pass0(
    const float* __restrict__ tab,
    const int*   __restrict__ idx,
    float* __restrict__ out,
    int B, int c1, int c2, int c3)
{
    __shared__ int stage[WPB * 32];
    int tid  = threadIdx.x;
    int lane = tid & 31;
    int node = blockIdx.x * WPB + (tid >> 5);
    if (node >= B) return;

    int r = __ldg(&idx[(size_t)node * K + lane]);
    int b = (r >= c1) + (r >= c2) + (r >= c3);          // bucket 0..3

    unsigned m0 = __ballot_sync(0xffffffffu, b == 0);
    unsigned m1 = __ballot_sync(0xffffffffu, b == 1);
    unsigned m2 = __ballot_sync(0xffffffffu, b == 2);
    unsigned m3 = __ballot_sync(0xffffffffu, b == 3);
    int n0 = __popc(m0), n1 = __popc(m1), n2 = __popc(m2);

    unsigned lt = (1u << lane) - 1u;
    int slot;
    if      (b == 0) slot = __popc(m0 & lt);
    else if (b == 1) slot = n0 + __popc(m1 & lt);
    else if (b == 2) slot = n0 + n1 + __popc(m2 & lt);
    else             slot = n0 + n1 + n2 + __popc(m3 & lt);

    int* sw = &stage[(tid >> 5) << 5];
    sw[slot] = r;
    __syncwarp();
    int v = sw[lane];                                   // reordered index

    g_sidx[(size_t)node * K + lane] = v;                // for passes 1-3
    if (lane == 0) g_cnt[node] = n0 | (n1 << 8) | (n2 << 16);

    float4 acc = dense_gather(tab, v, lane, 0, n0);     // bucket 0

    const float s = 1.0f / (float)K;
    acc.x *= s; acc.y *= s; acc.z *= s; acc.w *= s;
    reinterpret_cast<float4*>(out + (size_t)node * D)[lane] = acc;
}

// Passes 1-3: dense gather over one bucket, red.add into out.
template <int PASS>
__global__ __launch_bounds__(WPB * 32) void gather_pass(
    const float* __restrict__ tab, float* __restrict__ out, int B)
{
    int tid  = threadIdx.x;
    int lane = tid & 31;
    int node = blockIdx.x * WPB + (tid >> 5);
    if (node >= B) return;

    int v = g_sidx[(size_t)node * K + lane];
    int packed = g_cnt[node];
    int n0 =  packed        & 0xff;
    int n1 = (packed >> 8)  & 0xff;
    int n2 = (packed >> 16) & 0xff;

    int start, end;
    if      (PASS == 1) { start = n0;           end = n0 + n1; }
    else if (PASS == 2) { start = n0 + n1;      end = n0 + n1 + n2; }
    else                { start = n0 + n1 + n2; end = K; }

    float4 acc = dense_gather(tab, v, lane, start, end);

    const float s = 1.0f / (float)K;
    acc.x *= s; acc.y *= s; acc.z *= s; acc.w *= s;
    // Single writer per element; passes are stream-ordered -> deterministic.
    red_add_f4(&reinterpret_cast<float4*>(out + (size_t)node * D)[lane], acc);
}

extern "C" void kernel_launch(void* const* d_in, const int* in_sizes, int n_in,
                              void* d_out, int out_size)
{
    // Identify inputs by element count (robust to metadata ordering):
    // embed_table: 64,000,000 ; neigh_idx: 3,200,000 ; num_sample: 1
    long long max_sz = -1, mid_sz = -1;
    int ti = 0, ii = 1;
    for (int i = 0; i < n_in; ++i)
        if (in_sizes[i] > max_sz) { max_sz = in_sizes[i]; ti = i; }
    for (int i = 0; i < n_in; ++i)
        if (i != ti && in_sizes[i] > mid_sz) { mid_sz = in_sizes[i]; ii = i; }

    const float* tab = (const float*)d_in[ti];
    const int*   idx = (const int*)d_in[ii];
    float*       out = (float*)d_out;

    int B = out_size / D;                    // 100000
    int N = (int)(max_sz / D);               // 500000 table rows
    int chunk = (N + PASSES - 1) / PASSES;   // 125000 rows = 64MB

    int blocks = (B + WPB - 1) / WPB;

    partition_pass0<<<blocks, WPB * 32>>>(tab, idx, out, B,
                                          chunk, 2 * chunk, 3 * chunk);
    gather_pass<1><<<blocks, WPB * 32>>>(tab, out, B);
    gather_pass<2><<<blocks, WPB * 32>>>(tab, out, B);
    gather_pass<3><<<blocks, WPB * 32>>>(tab, out, B);
}

// round 10
// speedup vs baseline: 1.2807x; 1.2807x over previous
#include <cuda_runtime.h>
#include <cstdint>

// MeanAggregatorHead: out[b,:] = (1/K) * sum_k tab[idx[b,k],:]
// B=100000, K=32, N=500000, D=128, fp32 table, int32 indices.
//
// R10 = R8 gather (4-wide batching, regs~32, occ~78%, passes @ LTS cap)
//     + R9 fusion (partition folded into pass 0; no separate kernel,
//       no scratch round-trip before the first gather).
// Passes 1-3 red.add their scaled partial into out (single writer per
// element, stream-ordered passes -> deterministic).

constexpr int K       = 32;
constexpr int D       = 128;
constexpr int PASSES  = 4;
constexpr int MAX_B   = 100000;
constexpr int WPB     = 8;          // warps per block (256 threads)

__device__ int g_sidx[MAX_B * K];   // bucket-reordered indices (12.8MB)
__device__ int g_cnt [MAX_B];       // packed counts c0|c1<<8|c2<<16 (0.4MB)

__device__ __forceinline__ void red_add_f4(float4* p, float4 v) {
    asm volatile("red.global.add.v4.f32 [%0], {%1,%2,%3,%4};"
                 :: "l"(p), "f"(v.x), "f"(v.y), "f"(v.z), "f"(v.w) : "memory");
}

// Dense gather over slots [start, end) of warp-held reordered index v.
// 4-wide batching: 4 independent LDG.128 per iteration, regs stay ~32.
__device__ __forceinline__ float4 dense_gather(
    const float* __restrict__ tab, int v, int lane, int start, int end)
{
    float4 acc = make_float4(0.f, 0.f, 0.f, 0.f);
    int j = start;
    #pragma unroll 1
    for (; j + 4 <= end; j += 4) {
        int r0 = __shfl_sync(0xffffffffu, v, j);
        int r1 = __shfl_sync(0xffffffffu, v, j + 1);
        int r2 = __shfl_sync(0xffffffffu, v, j + 2);
        int r3 = __shfl_sync(0xffffffffu, v, j + 3);
        float4 a0 = __ldg(&reinterpret_cast<const float4*>(tab + (size_t)r0 * D)[lane]);
        float4 a1 = __ldg(&reinterpret_cast<const float4*>(tab + (size_t)r1 * D)[lane]);
        float4 a2 = __ldg(&reinterpret_cast<const float4*>(tab + (size_t)r2 * D)[lane]);
        float4 a3 = __ldg(&reinterpret_cast<const float4*>(tab + (size_t)r3 * D)[lane]);
        acc.x += (a0.x + a1.x) + (a2.x + a3.x);
        acc.y += (a0.y + a1.y) + (a2.y + a3.y);
        acc.z += (a0.z + a1.z) + (a2.z + a3.z);
        acc.w += (a0.w + a1.w) + (a2.w + a3.w);
    }
    #pragma unroll 1
    for (; j < end; ++j) {
        int r = __shfl_sync(0xffffffffu, v, j);
        float4 a = __ldg(&reinterpret_cast<const float4*>(tab + (size_t)r * D)[lane]);
        acc.x += a.x; acc.y += a.y; acc.z += a.z; acc.w += a.w;
    }
    return acc;
}

// Pass 0: partition + gather bucket 0, fused.
__global__ __launch_bounds__(WPB * 32) void partition_pass0(
    const float* __restrict__ tab,
    const int*   __restrict__ idx,
    float* __restrict__ out,
    int B, int c1, int c2, int c3)
{
    __shared__ int stage[WPB * 32];
    int tid  = threadIdx.x;
    int lane = tid & 31;
    int node = blockIdx.x * WPB + (tid >> 5);
    if (node >= B) return;

    int r = __ldg(&idx[(size_t)node * K + lane]);
    int b = (r >= c1) + (r >= c2) + (r >= c3);          // bucket 0..3

    unsigned m0 = __ballot_sync(0xffffffffu, b == 0);
    unsigned m1 = __ballot_sync(0xffffffffu, b == 1);
    unsigned m2 = __ballot_sync(0xffffffffu, b == 2);
    unsigned m3 = __ballot_sync(0xffffffffu, b == 3);
    int n0 = __popc(m0), n1 = __popc(m1), n2 = __popc(m2);

    unsigned lt = (1u << lane) - 1u;
    int slot;
    if      (b == 0) slot = __popc(m0 & lt);
    else if (b == 1) slot = n0 + __popc(m1 & lt);
    else if (b == 2) slot = n0 + n1 + __popc(m2 & lt);
    else             slot = n0 + n1 + n2 + __popc(m3 & lt);

    int* sw = &stage[(tid >> 5) << 5];
    sw[slot] = r;
    __syncwarp();
    int v = sw[lane];                                   // reordered index

    g_sidx[(size_t)node * K + lane] = v;                // for passes 1-3
    if (lane == 0) g_cnt[node] = n0 | (n1 << 8) | (n2 << 16);

    float4 acc = dense_gather(tab, v, lane, 0, n0);     // bucket 0

    const float s = 1.0f / (float)K;
    acc.x *= s; acc.y *= s; acc.z *= s; acc.w *= s;
    reinterpret_cast<float4*>(out + (size_t)node * D)[lane] = acc;
}

// Passes 1-3: dense gather over one bucket, red.add into out.
template <int PASS>
__global__ __launch_bounds__(WPB * 32) void gather_pass(
    const float* __restrict__ tab, float* __restrict__ out, int B)
{
    int tid  = threadIdx.x;
    int lane = tid & 31;
    int node = blockIdx.x * WPB + (tid >> 5);
    if (node >= B) return;

    int v = g_sidx[(size_t)node * K + lane];
    int packed = g_cnt[node];
    int n0 =  packed        & 0xff;
    int n1 = (packed >> 8)  & 0xff;
    int n2 = (packed >> 16) & 0xff;

    int start, end;
    if      (PASS == 1) { start = n0;           end = n0 + n1; }
    else if (PASS == 2) { start = n0 + n1;      end = n0 + n1 + n2; }
    else                { start = n0 + n1 + n2; end = K; }

    float4 acc = dense_gather(tab, v, lane, start, end);

    const float s = 1.0f / (float)K;
    acc.x *= s; acc.y *= s; acc.z *= s; acc.w *= s;
    // Single writer per element; passes are stream-ordered -> deterministic.
    red_add_f4(&reinterpret_cast<float4*>(out + (size_t)node * D)[lane], acc);
}

extern "C" void kernel_launch(void* const* d_in, const int* in_sizes, int n_in,
                              void* d_out, int out_size)
{
    // Identify inputs by element count (robust to metadata ordering):
    // embed_table: 64,000,000 ; neigh_idx: 3,200,000 ; num_sample: 1
    long long max_sz = -1, mid_sz = -1;
    int ti = 0, ii = 1;
    for (int i = 0; i < n_in; ++i)
        if (in_sizes[i] > max_sz) { max_sz = in_sizes[i]; ti = i; }
    for (int i = 0; i < n_in; ++i)
        if (i != ti && in_sizes[i] > mid_sz) { mid_sz = in_sizes[i]; ii = i; }

    const float* tab = (const float*)d_in[ti];
    const int*   idx = (const int*)d_in[ii];
    float*       out = (float*)d_out;

    int B = out_size / D;                    // 100000
    int N = (int)(max_sz / D);               // 500000 table rows
    int chunk = (N + PASSES - 1) / PASSES;   // 125000 rows = 64MB

    int blocks = (B + WPB - 1) / WPB;

    partition_pass0<<<blocks, WPB * 32>>>(tab, idx, out, B,
                                          chunk, 2 * chunk, 3 * chunk);
    gather_pass<1><<<blocks, WPB * 32>>>(tab, out, B);
    gather_pass<2><<<blocks, WPB * 32>>>(tab, out, B);
    gather_pass<3><<<blocks, WPB * 32>>>(tab, out, B);
}